// round 8
// baseline (speedup 1.0000x reference)
#include <cuda_runtime.h>

// Problem constants (fixed by the dataset)
#define B_ 4
#define M_ 16384
#define N_ 32768
#define K_ 16
#define ROWS (B_ * N_)          // 131072
#define TILE 128
#define TILES (ROWS / TILE)     // 1024 tiles per path
#define OUTC 131
#define EPSV 1e-5f
#define AS 68                   // A tile row stride in floats (mult of 4, odd/4 banks)

typedef unsigned long long ull;

// Scratch: pre-BN activations for both paths + global stat accumulators.
__device__ float g_Y1[(size_t)ROWS * 64];
__device__ float g_Y2[(size_t)ROWS * 64];
__device__ float g_stats[256];        // [sum1(64), sq1(64), sum2(64), sq2(64)]
__device__ unsigned int g_done = 0;   // finalize completion counter

// ---- packed f32x2 helpers (Blackwell FFMA2: 2 FMA per instruction) ----
__device__ __forceinline__ void ffma2(ull& acc, ull a, ull b) {
    asm volatile("fma.rn.f32x2 %0, %1, %2, %0;" : "+l"(acc) : "l"(a), "l"(b));
}
__device__ __forceinline__ ull pack2(float x, float y) {
    ull r;
    asm("mov.b64 %0, {%1, %2};" : "=l"(r) : "f"(x), "f"(y));
    return r;
}
__device__ __forceinline__ float2 unpack2(ull v) {
    float2 f;
    asm("mov.b64 {%0, %1}, %2;" : "=f"(f.x), "=f"(f.y) : "l"(v));
    return f;
}

// dynamic shared layout (floats):
//   A      [128][AS]   : 128*68 = 8704
//   W      [64][64]    : 4096   @ 8704
//   bias   [64]        : 64     @ 12800
//   sstats [128]       : 128    @ 12864
//   total 12992 floats = 51968 bytes  (4 CTAs/SM fits 228KB carveout)
#define SM_W 8704
#define SM_B 12800
#define SM_S 12864
#define SM_FLOATS 12992

// Pass 1: even blocks do gather+maxpool+GEMM(W1); odd blocks do skip GEMM(W2).
// Writes pre-BN Y and accumulates per-channel sum/sumsq.
__global__ void __launch_bounds__(128, 4) fused_pass1(
    const float* __restrict__ curr_feat,
    const float* __restrict__ skip_feat,
    const int* __restrict__ idxs,          // int32 (JAX x64 disabled)
    const float* __restrict__ W1, const float* __restrict__ b1,
    const float* __restrict__ W2, const float* __restrict__ b2)
{
    extern __shared__ float sm[];
    float* A      = sm;
    float* Wsh    = sm + SM_W;
    float* bsh    = sm + SM_B;
    float* sstats = sm + SM_S;

    const int tid   = threadIdx.x;
    const int bid   = blockIdx.x;
    const bool path2 = (bid & 1);
    const int  trow  = (bid >> 1) * TILE;

    const float* W    = path2 ? W2 : W1;
    const float* bias = path2 ? b2 : b1;
    float*       Yout = path2 ? g_Y2 : g_Y1;
    const int statoff = path2 ? 128 : 0;

    // stage W (float4) + bias + zero stat partials
    {
        const float4* Wg  = (const float4*)W;
        float4*       Ws4 = (float4*)Wsh;
        #pragma unroll
        for (int i = 0; i < 8; ++i) Ws4[tid + 128 * i] = __ldg(&Wg[tid + 128 * i]);
    }
    if (tid < 64) bsh[tid] = bias[tid];
    sstats[tid] = 0.0f;

    // ---------- Phase A: stage input tile A[128][64] into shared ----------
    if (!path2) {
        // gather + max-pool: 2 rows per warp (16 lanes each, float4 = 4 channels/lane)
        const int warp = tid >> 5, lane = tid & 31;
        const int half = lane >> 4, hl = lane & 15;
        const int b = trow >> 15;   // 32768 rows per batch; tiles never cross batches
        const float4* feat4 = (const float4*)curr_feat + (size_t)b * M_ * 16;
        for (int rp = warp; rp < 64; rp += 4) {
            const int rloc = 2 * rp + half;
            const int row  = trow + rloc;
            int myidx = idxs[(size_t)row * K_ + hl];
            float4 p = make_float4(-3.4e38f, -3.4e38f, -3.4e38f, -3.4e38f);
            #pragma unroll
            for (int k = 0; k < K_; ++k) {
                int id = __shfl_sync(0xffffffffu, myidx, (half << 4) | k) & (M_ - 1);
                float4 v = __ldg(&feat4[(size_t)id * 16 + hl]);
                p.x = fmaxf(p.x, v.x);
                p.y = fmaxf(p.y, v.y);
                p.z = fmaxf(p.z, v.z);
                p.w = fmaxf(p.w, v.w);
            }
            *(float4*)&A[rloc * AS + 4 * hl] = p;
        }
    } else {
        const float4* sf4 = (const float4*)skip_feat + (size_t)trow * 16;
        #pragma unroll
        for (int i = 0; i < 16; ++i) {
            int m = tid + 128 * i;          // 0..2047
            int r = m >> 4, c = m & 15;
            *(float4*)&A[r * AS + 4 * c] = __ldg(&sf4[m]);
        }
    }
    __syncthreads();

    // ---------- Phase B: GEMM, 8 rows x 8 cols per thread (rows strided 16) ----
    const int tx = tid & 7;     // cols 8*tx .. 8*tx+7
    const int ty = tid >> 3;    // rows ty + 16*i

    ull acc[8][4];
    {
        const ull* bp = (const ull*)(bsh + 8 * tx);
        ull b0 = bp[0], b1v = bp[1], b2v = bp[2], b3v = bp[3];
        #pragma unroll
        for (int i = 0; i < 8; ++i) {
            acc[i][0] = b0; acc[i][1] = b1v; acc[i][2] = b2v; acc[i][3] = b3v;
        }
    }

    #pragma unroll 2
    for (int kc = 0; kc < 64; kc += 4) {
        float4 a4[8];
        #pragma unroll
        for (int i = 0; i < 8; ++i)
            a4[i] = *(const float4*)&A[(ty + 16 * i) * AS + kc];
        #pragma unroll
        for (int j = 0; j < 4; ++j) {
            const ull* wr = (const ull*)(Wsh + (kc + j) * 64 + 8 * tx);
            ull w0 = wr[0], w1 = wr[1], w2 = wr[2], w3 = wr[3];
            #pragma unroll
            for (int i = 0; i < 8; ++i) {
                float a = (j == 0) ? a4[i].x : (j == 1) ? a4[i].y
                        : (j == 2) ? a4[i].z : a4[i].w;
                ull aa = pack2(a, a);
                ffma2(acc[i][0], aa, w0);
                ffma2(acc[i][1], aa, w1);
                ffma2(acc[i][2], aa, w2);
                ffma2(acc[i][3], aa, w3);
            }
        }
    }

    // ---------- Phase C: store Y (float4), accumulate sum / sumsq ----------
    float s[8] = {0, 0, 0, 0, 0, 0, 0, 0};
    float q[8] = {0, 0, 0, 0, 0, 0, 0, 0};
    #pragma unroll
    for (int i = 0; i < 8; ++i) {
        const int row = trow + ty + 16 * i;
        float2 y0 = unpack2(acc[i][0]);
        float2 y1 = unpack2(acc[i][1]);
        float2 y2 = unpack2(acc[i][2]);
        float2 y3 = unpack2(acc[i][3]);
        float4* dst = (float4*)(Yout + (size_t)row * 64 + 8 * tx);
        dst[0] = make_float4(y0.x, y0.y, y1.x, y1.y);
        dst[1] = make_float4(y2.x, y2.y, y3.x, y3.y);
        s[0] += y0.x; q[0] += y0.x * y0.x;
        s[1] += y0.y; q[1] += y0.y * y0.y;
        s[2] += y1.x; q[2] += y1.x * y1.x;
        s[3] += y1.y; q[3] += y1.y * y1.y;
        s[4] += y2.x; q[4] += y2.x * y2.x;
        s[5] += y2.y; q[5] += y2.y * y2.y;
        s[6] += y3.x; q[6] += y3.x * y3.x;
        s[7] += y3.y; q[7] += y3.y * y3.y;
    }
    #pragma unroll
    for (int j = 0; j < 8; ++j) {
        atomicAdd(&sstats[8 * tx + j],      s[j]);
        atomicAdd(&sstats[64 + 8 * tx + j], q[j]);
    }
    __syncthreads();
    atomicAdd(&g_stats[statoff + tid], sstats[tid]);
}

// Pass 2: finalize BN stats, normalize + ReLU, concat with skip_coords.
// Last block resets g_stats (and g_done) so every graph replay starts clean.
__global__ void __launch_bounds__(256) finalize_k(
    const float* __restrict__ skip_coords,
    const float* __restrict__ g1, const float* __restrict__ be1,
    const float* __restrict__ g2, const float* __restrict__ be2,
    float* __restrict__ out)
{
    __shared__ float sc1[64], sh1[64], sc2[64], sh2[64];
    const int tid = threadIdx.x;
    if (tid < 64) {
        const float inv = 1.0f / (float)ROWS;
        float mu  = g_stats[tid] * inv;
        float var = g_stats[64 + tid] * inv - mu * mu;
        float sv  = g1[tid] * rsqrtf(var + EPSV);
        sc1[tid] = sv;
        sh1[tid] = be1[tid] - mu * sv;
    } else if (tid < 128) {
        const int j = tid - 64;
        const float inv = 1.0f / (float)ROWS;
        float mu  = g_stats[128 + j] * inv;
        float var = g_stats[192 + j] * inv - mu * mu;
        float sv  = g2[j] * rsqrtf(var + EPSV);
        sc2[j] = sv;
        sh2[j] = be2[j] - mu * sv;
    }
    __syncthreads();

    // all of this block's g_stats reads are done -> safe to count & reset
    if (tid == 0) {
        unsigned int old = atomicAdd(&g_done, 1u);
        if (old == gridDim.x - 1) {
            g_done = 0;
            #pragma unroll
            for (int i = 0; i < 256; ++i) g_stats[i] = 0.0f;
        }
    }

    const int warp = tid >> 5, lane = tid & 31;
    const int gw = blockIdx.x * 8 + warp;
    const int nw = gridDim.x * 8;
    for (int row = gw; row < ROWS; row += nw) {
        const float* y1 = g_Y1 + (size_t)row * 64;
        const float* y2 = g_Y2 + (size_t)row * 64;
        float* o = out + (size_t)row * OUTC;
        #pragma unroll
        for (int s = 0; s < 5; ++s) {
            int e = lane + 32 * s;
            if (e >= OUTC) break;
            float v;
            if (e < 3) {
                v = __ldg(&skip_coords[(size_t)row * 3 + e]);
            } else if (e < 67) {
                int c = e - 3;
                v = fmaxf(__ldg(&y1[c]) * sc1[c] + sh1[c], 0.0f);
            } else {
                int c = e - 67;
                v = fmaxf(__ldg(&y2[c]) * sc2[c] + sh2[c], 0.0f);
            }
            o[e] = v;
        }
    }
}

extern "C" void kernel_launch(void* const* d_in, const int* in_sizes, int n_in,
                              void* d_out, int out_size) {
    // metadata order: curr_coords, curr_feat, skip_coords, skip_feat,
    // upsampling_idxs(int32), W1, b1, g1, beta1, W2, b2, g2, beta2
    const float* curr_feat   = (const float*)d_in[1];
    const float* skip_coords = (const float*)d_in[2];
    const float* skip_feat   = (const float*)d_in[3];
    const int*   idxs        = (const int*)d_in[4];
    const float* W1  = (const float*)d_in[5];
    const float* b1  = (const float*)d_in[6];
    const float* g1  = (const float*)d_in[7];
    const float* be1 = (const float*)d_in[8];
    const float* W2  = (const float*)d_in[9];
    const float* b2  = (const float*)d_in[10];
    const float* g2  = (const float*)d_in[11];
    const float* be2 = (const float*)d_in[12];
    float* out = (float*)d_out;

    cudaFuncSetAttribute(fused_pass1, cudaFuncAttributeMaxDynamicSharedMemorySize,
                         SM_FLOATS * sizeof(float));

    fused_pass1<<<2 * TILES, 128, SM_FLOATS * sizeof(float)>>>(
        curr_feat, skip_feat, idxs, W1, b1, W2, b2);
    finalize_k<<<2048, 256>>>(skip_coords, g1, be1, g2, be2, out);
}